// round 2
// baseline (speedup 1.0000x reference)
#include <cuda_runtime.h>

#define EPS 1e-6f
#define Q 128
#define HW 65536            // 256*256
#define NW 8                // columns (warps) per block
#define THREADS 256

__device__ float g_wt[Q];   // softmax(weights) * 128, precomputed once

// ---------------------------------------------------------------------------
// Prep kernel: one warp computes wt = softmax(weights) * 128
// ---------------------------------------------------------------------------
__global__ void softmax_wt_kernel(const float* __restrict__ w) {
    int l = threadIdx.x;                       // 0..31
    float v0 = w[l * 4 + 0], v1 = w[l * 4 + 1];
    float v2 = w[l * 4 + 2], v3 = w[l * 4 + 3];
    float m = fmaxf(fmaxf(v0, v1), fmaxf(v2, v3));
    #pragma unroll
    for (int o = 16; o; o >>= 1) m = fmaxf(m, __shfl_xor_sync(0xffffffffu, m, o));
    float e0 = expf(v0 - m), e1 = expf(v1 - m);
    float e2 = expf(v2 - m), e3 = expf(v3 - m);
    float s = e0 + e1 + e2 + e3;
    #pragma unroll
    for (int o = 16; o; o >>= 1) s += __shfl_xor_sync(0xffffffffu, s, o);
    float scale = 128.0f / s;
    g_wt[l * 4 + 0] = e0 * scale;
    g_wt[l * 4 + 1] = e1 * scale;
    g_wt[l * 4 + 2] = e2 * scale;
    g_wt[l * 4 + 3] = e3 * scale;
}

// ---------------------------------------------------------------------------
// Main kernel: block = 256 threads = 8 warps; each warp ranks one column of
// 128 values (along dim q). XOR-swizzled SMEM transpose, warp-register
// bitonic sort (descending), binary-search rank, exact tie fixup.
// ---------------------------------------------------------------------------
__global__ void __launch_bounds__(THREADS) rank_weight_kernel(
        const float* __restrict__ x, float* __restrict__ out) {
    __shared__ __align__(16) float A[NW * Q];   // original values (transposed), later reused for output
    __shared__ __align__(16) float S[NW * Q];   // sorted values per column
    __shared__ float wt_s[Q];

    int t = threadIdx.x;
    if (t < Q) wt_s[t] = g_wt[t];

    // Column base: 8 consecutive flattened (b, h*w) columns per block.
    long long c0  = (long long)blockIdx.x * NW;
    int       b   = (int)(c0 >> 16);            // HW = 65536 columns per batch
    int       rem = (int)(c0 & (HW - 1));
    const float* xb = x   + (long long)b * (Q * (long long)HW) + rem;
    float*       ob = out + (long long)b * (Q * (long long)HW) + rem;

    // ---- Phase 1: coalesced load, transpose into swizzled SMEM ----
    {
        int q = t >> 1;            // 128 rows, 2 threads per row
        int g = t & 1;             // which float4 group: w_local = 4g .. 4g+3
        float4 f = *reinterpret_cast<const float4*>(xb + (long long)q * HW + 4 * g);
        float vv[4] = {f.x, f.y, f.z, f.w};
        #pragma unroll
        for (int j = 0; j < 4; j++) {
            int w = 4 * g + j;
            A[w * Q + (q ^ (w << 2))] = vv[j];
        }
    }
    __syncthreads();

    int lane = t & 31;
    int w    = t >> 5;             // warp id = local column
    int sw   = w << 2;             // swizzle constant for this column

    // ---- Phase 2: read column (q = 4*lane + r), sort descending ----
    float4 cv = *reinterpret_cast<const float4*>(&A[w * Q + ((lane << 2) ^ sw)]);
    float v[4]    = {cv.x, cv.y, cv.z, cv.w};
    float orig[4] = {cv.x, cv.y, cv.z, cv.w};

    #pragma unroll
    for (int k = 2; k <= 128; k <<= 1) {
        #pragma unroll
        for (int j = k >> 1; j > 0; j >>= 1) {
            if (j >= 4) {
                // cross-lane butterfly; direction uniform across a thread's 4 slots
                #pragma unroll
                for (int r = 0; r < 4; r++) {
                    float o  = __shfl_xor_sync(0xffffffffu, v[r], j >> 2);
                    int   id = (lane << 2) + r;
                    bool keep_max = (((id & k) == 0) == ((id & j) == 0));
                    float mx = fmaxf(v[r], o), mn = fminf(v[r], o);
                    v[r] = keep_max ? mx : mn;
                }
            } else if (j == 2) {
                #pragma unroll
                for (int r = 0; r < 2; r++) {
                    int  id = (lane << 2) + r;          // (id & 2) == 0 here
                    bool keep_max = ((id & k) == 0);
                    float a = v[r], bb = v[r + 2];
                    float mx = fmaxf(a, bb), mn = fminf(a, bb);
                    v[r]     = keep_max ? mx : mn;
                    v[r + 2] = keep_max ? mn : mx;
                }
            } else {  // j == 1
                #pragma unroll
                for (int r = 0; r < 4; r += 2) {
                    int  id = (lane << 2) + r;          // (id & 1) == 0 here
                    bool keep_max = ((id & k) == 0);
                    float a = v[r], bb = v[r + 1];
                    float mx = fmaxf(a, bb), mn = fminf(a, bb);
                    v[r]     = keep_max ? mx : mn;
                    v[r + 1] = keep_max ? mn : mx;
                }
            }
        }
    }

    // store sorted column (descending: S[p] = p-th largest)
    *reinterpret_cast<float4*>(&S[w * Q + ((lane << 2) ^ sw)]) =
        make_float4(v[0], v[1], v[2], v[3]);
    __syncwarp();

    // ---- Phase 3: rank via binary search (count strictly greater), tie fixup ----
    const float* Scol = &S[w * Q];
    const float* Acol = &A[w * Q];
    float res[4];
    #pragma unroll
    for (int r = 0; r < 4; r++) {
        float xv  = orig[r];
        int   pos = 0;                        // will equal #{j : x_j > xv}
        #pragma unroll
        for (int step = 64; step >= 1; step >>= 1) {
            if (Scol[(pos + step - 1) ^ sw] > xv) pos += step;
        }
        int rank = pos;
        // exact stable tie handling (rare): duplicates sit at pos, pos+1, ...
        if (pos + 1 < Q && Scol[(pos + 1) ^ sw] == xv) {
            int i = (lane << 2) + r;          // this element's original q index
            int eq = 0;
            for (int jj = 0; jj < i; jj++)
                eq += (Acol[jj ^ sw] == xv) ? 1 : 0;
            rank = pos + eq;
        }
        float rs;
        asm("rsqrt.approx.f32 %0, %1;" : "=f"(rs) : "f"(__fmaf_rn(xv, xv, EPS)));
        res[r] = wt_s[rank] * rs;
    }

    // all lanes of this warp are done reading Acol -> safe to overwrite own column
    __syncwarp();
    *reinterpret_cast<float4*>(&A[w * Q + ((lane << 2) ^ sw)]) =
        make_float4(res[0], res[1], res[2], res[3]);
    __syncthreads();

    // ---- Phase 4: transpose back, coalesced store ----
    {
        int q = t >> 1;
        int g = t & 1;
        float o0 = A[(4 * g + 0) * Q + (q ^ ((4 * g + 0) << 2))];
        float o1 = A[(4 * g + 1) * Q + (q ^ ((4 * g + 1) << 2))];
        float o2 = A[(4 * g + 2) * Q + (q ^ ((4 * g + 2) << 2))];
        float o3 = A[(4 * g + 3) * Q + (q ^ ((4 * g + 3) << 2))];
        *reinterpret_cast<float4*>(ob + (long long)q * HW + 4 * g) =
            make_float4(o0, o1, o2, o3);
    }
}

// ---------------------------------------------------------------------------
extern "C" void kernel_launch(void* const* d_in, const int* in_sizes, int n_in,
                              void* d_out, int out_size) {
    const float* x  = (const float*)d_in[0];
    const float* wt = (const float*)d_in[1];
    if (n_in >= 2 && in_sizes[0] == Q) {  // defensive: metadata order swap
        const float* tmp = x; x = wt; wt = tmp;
    }
    float* out = (float*)d_out;

    softmax_wt_kernel<<<1, 32>>>(wt);

    // total columns = 8 * 256 * 256 = 524288; NW columns per block
    int total_cols = 8 * HW;
    int blocks = total_cols / NW;          // 65536
    rank_weight_kernel<<<blocks, THREADS>>>(x, out);
}

// round 3
// speedup vs baseline: 1.0031x; 1.0031x over previous
#include <cuda_runtime.h>

#define EPS 1e-6f
#define Q 128
#define HW 65536            // 256*256
#define NW 8                // columns (warps) per block
#define THREADS 256

__device__ float g_wt[Q];   // softmax(weights) * 128, precomputed once

// ---------------------------------------------------------------------------
// Prep kernel: one warp computes wt = softmax(weights) * 128
// ---------------------------------------------------------------------------
__global__ void softmax_wt_kernel(const float* __restrict__ w) {
    int l = threadIdx.x;                       // 0..31
    float v0 = w[l * 4 + 0], v1 = w[l * 4 + 1];
    float v2 = w[l * 4 + 2], v3 = w[l * 4 + 3];
    float m = fmaxf(fmaxf(v0, v1), fmaxf(v2, v3));
    #pragma unroll
    for (int o = 16; o; o >>= 1) m = fmaxf(m, __shfl_xor_sync(0xffffffffu, m, o));
    float e0 = expf(v0 - m), e1 = expf(v1 - m);
    float e2 = expf(v2 - m), e3 = expf(v3 - m);
    float s = e0 + e1 + e2 + e3;
    #pragma unroll
    for (int o = 16; o; o >>= 1) s += __shfl_xor_sync(0xffffffffu, s, o);
    float scale = 128.0f / s;
    g_wt[l * 4 + 0] = e0 * scale;
    g_wt[l * 4 + 1] = e1 * scale;
    g_wt[l * 4 + 2] = e2 * scale;
    g_wt[l * 4 + 3] = e3 * scale;
}

// ---------------------------------------------------------------------------
// Main kernel: block = 256 threads = 8 warps; each warp ranks one column of
// 128 values (along dim q). XOR-swizzled SMEM transpose, warp-register
// bitonic sort (descending), binary-search rank, exact tie fixup.
// ---------------------------------------------------------------------------
__global__ void __launch_bounds__(THREADS) rank_weight_kernel(
        const float* __restrict__ x, float* __restrict__ out) {
    __shared__ __align__(16) float A[NW * Q];   // original values (transposed), later reused for output
    __shared__ __align__(16) float S[NW * Q];   // sorted values per column
    __shared__ float wt_s[Q];

    int t = threadIdx.x;
    if (t < Q) wt_s[t] = g_wt[t];

    // Column base: 8 consecutive flattened (b, h*w) columns per block.
    long long c0  = (long long)blockIdx.x * NW;
    int       b   = (int)(c0 >> 16);            // HW = 65536 columns per batch
    int       rem = (int)(c0 & (HW - 1));
    const float* xb = x   + (long long)b * (Q * (long long)HW) + rem;
    float*       ob = out + (long long)b * (Q * (long long)HW) + rem;

    // ---- Phase 1: coalesced load, transpose into swizzled SMEM ----
    {
        int q = t >> 1;            // 128 rows, 2 threads per row
        int g = t & 1;             // which float4 group: w_local = 4g .. 4g+3
        float4 f = *reinterpret_cast<const float4*>(xb + (long long)q * HW + 4 * g);
        float vv[4] = {f.x, f.y, f.z, f.w};
        #pragma unroll
        for (int j = 0; j < 4; j++) {
            int w = 4 * g + j;
            A[w * Q + (q ^ (w << 2))] = vv[j];
        }
    }
    __syncthreads();

    int lane = t & 31;
    int w    = t >> 5;             // warp id = local column
    int sw   = w << 2;             // swizzle constant for this column

    // ---- Phase 2: read column (q = 4*lane + r), sort descending ----
    float4 cv = *reinterpret_cast<const float4*>(&A[w * Q + ((lane << 2) ^ sw)]);
    float v[4]    = {cv.x, cv.y, cv.z, cv.w};
    float orig[4] = {cv.x, cv.y, cv.z, cv.w};

    #pragma unroll
    for (int k = 2; k <= 128; k <<= 1) {
        #pragma unroll
        for (int j = k >> 1; j > 0; j >>= 1) {
            if (j >= 4) {
                // cross-lane butterfly; direction uniform across a thread's 4 slots
                #pragma unroll
                for (int r = 0; r < 4; r++) {
                    float o  = __shfl_xor_sync(0xffffffffu, v[r], j >> 2);
                    int   id = (lane << 2) + r;
                    bool keep_max = (((id & k) == 0) == ((id & j) == 0));
                    float mx = fmaxf(v[r], o), mn = fminf(v[r], o);
                    v[r] = keep_max ? mx : mn;
                }
            } else if (j == 2) {
                #pragma unroll
                for (int r = 0; r < 2; r++) {
                    int  id = (lane << 2) + r;          // (id & 2) == 0 here
                    bool keep_max = ((id & k) == 0);
                    float a = v[r], bb = v[r + 2];
                    float mx = fmaxf(a, bb), mn = fminf(a, bb);
                    v[r]     = keep_max ? mx : mn;
                    v[r + 2] = keep_max ? mn : mx;
                }
            } else {  // j == 1
                #pragma unroll
                for (int r = 0; r < 4; r += 2) {
                    int  id = (lane << 2) + r;          // (id & 1) == 0 here
                    bool keep_max = ((id & k) == 0);
                    float a = v[r], bb = v[r + 1];
                    float mx = fmaxf(a, bb), mn = fminf(a, bb);
                    v[r]     = keep_max ? mx : mn;
                    v[r + 1] = keep_max ? mn : mx;
                }
            }
        }
    }

    // store sorted column (descending: S[p] = p-th largest)
    *reinterpret_cast<float4*>(&S[w * Q + ((lane << 2) ^ sw)]) =
        make_float4(v[0], v[1], v[2], v[3]);
    __syncwarp();

    // ---- Phase 3: rank via binary search (count strictly greater), tie fixup ----
    const float* Scol = &S[w * Q];
    const float* Acol = &A[w * Q];
    float res[4];
    #pragma unroll
    for (int r = 0; r < 4; r++) {
        float xv  = orig[r];
        int   pos = 0;                        // will equal #{j : x_j > xv}
        #pragma unroll
        for (int step = 64; step >= 1; step >>= 1) {
            if (Scol[(pos + step - 1) ^ sw] > xv) pos += step;
        }
        int rank = pos;
        // exact stable tie handling (rare): duplicates sit at pos, pos+1, ...
        if (pos + 1 < Q && Scol[(pos + 1) ^ sw] == xv) {
            int i = (lane << 2) + r;          // this element's original q index
            int eq = 0;
            for (int jj = 0; jj < i; jj++)
                eq += (Acol[jj ^ sw] == xv) ? 1 : 0;
            rank = pos + eq;
        }
        float rs;
        asm("rsqrt.approx.f32 %0, %1;" : "=f"(rs) : "f"(__fmaf_rn(xv, xv, EPS)));
        res[r] = wt_s[rank] * rs;
    }

    // all lanes of this warp are done reading Acol -> safe to overwrite own column
    __syncwarp();
    *reinterpret_cast<float4*>(&A[w * Q + ((lane << 2) ^ sw)]) =
        make_float4(res[0], res[1], res[2], res[3]);
    __syncthreads();

    // ---- Phase 4: transpose back, coalesced store ----
    {
        int q = t >> 1;
        int g = t & 1;
        float o0 = A[(4 * g + 0) * Q + (q ^ ((4 * g + 0) << 2))];
        float o1 = A[(4 * g + 1) * Q + (q ^ ((4 * g + 1) << 2))];
        float o2 = A[(4 * g + 2) * Q + (q ^ ((4 * g + 2) << 2))];
        float o3 = A[(4 * g + 3) * Q + (q ^ ((4 * g + 3) << 2))];
        *reinterpret_cast<float4*>(ob + (long long)q * HW + 4 * g) =
            make_float4(o0, o1, o2, o3);
    }
}

// ---------------------------------------------------------------------------
extern "C" void kernel_launch(void* const* d_in, const int* in_sizes, int n_in,
                              void* d_out, int out_size) {
    const float* x  = (const float*)d_in[0];
    const float* wt = (const float*)d_in[1];
    if (n_in >= 2 && in_sizes[0] == Q) {  // defensive: metadata order swap
        const float* tmp = x; x = wt; wt = tmp;
    }
    float* out = (float*)d_out;

    softmax_wt_kernel<<<1, 32>>>(wt);

    // total columns = 8 * 256 * 256 = 524288; NW columns per block
    int total_cols = 8 * HW;
    int blocks = total_cols / NW;          // 65536
    rank_weight_kernel<<<blocks, THREADS>>>(x, out);
}